// round 14
// baseline (speedup 1.0000x reference)
#include <cuda_runtime.h>

// fired[b,s,r] = x[...,i] * x[...,5+j] * x[...,10+k],  r = i*25 + j*5 + k
// Exact zeros in x act as identity (reference: where(rpu==0,1,rpu)).
//
// Frozen shape (v11): 2048 CTAs x 128 thr, thread t = rule t, 16 positions
// per CTA, immediate-offset LDS, __ldg staging, __stcs streaming stores.
// v12 micro-trim: manual 4-position batching — 12 LDS issued back-to-back,
// then 4 product chains + 4 stores, so each LDS batch overlaps the next
// batch's latency instead of tight load/use interleave at 32 regs.

static constexpr int F    = 15;           // membership functions per position
static constexpr int R    = 125;          // rules per position
static constexpr int G    = 16;           // positions per CTA
static constexpr int NLD4 = G * F / 4;    // 60 float4 input loads per CTA

__global__ void __launch_bounds__(128, 8)
rules_fire_v12(const float4* __restrict__ x4, float* __restrict__ out)
{
    __shared__ float sx[G * F];           // 240 floats (16 rows x 15)

    const int t   = threadIdx.x;
    const int grp = blockIdx.x;

    // Stage 16x15 inputs (threads 0..59), zero->1 fix at load.
    if (t < NLD4) {
        float4 v = __ldg(&x4[(size_t)grp * NLD4 + t]);
        v.x = (v.x == 0.0f) ? 1.0f : v.x;
        v.y = (v.y == 0.0f) ? 1.0f : v.y;
        v.z = (v.z == 0.0f) ? 1.0f : v.z;
        v.w = (v.w == 0.0f) ? 1.0f : v.w;
        reinterpret_cast<float4*>(sx)[t] = v;
    }
    __syncthreads();

    if (t < R) {
        // One rule decomposition per thread — the only divisions in the kernel.
        const int q = t / 5;
        const int k = t - 5 * q;          // t % 5
        const int i = q / 5;
        const int j = q - 5 * i;          // (t/5) % 5

        const int oa = i;
        const int ob = 5 + j;
        const int oc = 10 + k;

        float* o = out + (size_t)grp * G * R + t;   // + p*R via immediates

        // 4 batches of 4 positions: 12 LDS back-to-back, then 4 chains + stores.
        #pragma unroll
        for (int bb = 0; bb < G; bb += 4) {
            float a0, b0, c0, a1, b1, c1, a2, b2, c2, a3, b3, c3;
            {
                const int r0 = (bb + 0) * F, r1 = (bb + 1) * F,
                          r2 = (bb + 2) * F, r3 = (bb + 3) * F;
                a0 = sx[r0 + oa]; b0 = sx[r0 + ob]; c0 = sx[r0 + oc];
                a1 = sx[r1 + oa]; b1 = sx[r1 + ob]; c1 = sx[r1 + oc];
                a2 = sx[r2 + oa]; b2 = sx[r2 + ob]; c2 = sx[r2 + oc];
                a3 = sx[r3 + oa]; b3 = sx[r3 + ob]; c3 = sx[r3 + oc];
            }
            __stcs(o + (bb + 0) * R, a0 * b0 * c0);
            __stcs(o + (bb + 1) * R, a1 * b1 * c1);
            __stcs(o + (bb + 2) * R, a2 * b2 * c2);
            __stcs(o + (bb + 3) * R, a3 * b3 * c3);
        }
    }
}

// Scalar fallback for positions past the last full group (unused for B=16,S=2048).
__global__ void rules_fire_tail(const float* __restrict__ x, float* __restrict__ out,
                                int pos0, int npos)
{
    const int pos = pos0 + blockIdx.x;
    if (pos >= npos) return;
    __shared__ float sxt[F + 1];
    const int t = threadIdx.x;
    if (t < F) {
        float v = x[(size_t)pos * F + t];
        sxt[t] = (v == 0.0f) ? 1.0f : v;
    }
    __syncthreads();
    if (t < R) {
        const int i = t / 25, j = (t / 5) % 5, k = t % 5;
        out[(size_t)pos * R + t] = sxt[i] * sxt[5 + j] * sxt[10 + k];
    }
}

extern "C" void kernel_launch(void* const* d_in, const int* in_sizes, int n_in,
                              void* d_out, int out_size)
{
    const float* x = (const float*)d_in[0];   // (B, S, 15) float32
    float* out = (float*)d_out;               // (B, S, 125) float32

    const int npos    = in_sizes[0] / F;      // 32768
    const int ngroups = npos / G;             // 2048
    if (ngroups > 0)
        rules_fire_v12<<<ngroups, 128>>>((const float4*)x, out);

    const int tail = npos - ngroups * G;
    if (tail > 0)
        rules_fire_tail<<<tail, 128>>>(x, out, ngroups * G, npos);
}

// round 16
// speedup vs baseline: 1.0257x; 1.0257x over previous
#include <cuda_runtime.h>

// fired[b,s,r] = x[...,i] * x[...,5+j] * x[...,10+k],  r = i*25 + j*5 + k
// Exact zeros in x act as identity (reference: where(rpu==0,1,rpu)).
//
// FINAL (v11, measured optimum across 12 variants; kernel 6.496us):
// 2048 CTAs x 128 thr, thread t = rule t (one decomposition per thread),
// 16 positions per CTA, immediate-offset LDS, __ldg staging, __stcs
// streaming stores, no occupancy clamp (ptxas picks regs=32, occ 16).
// Plateau evidence R2-R10: ~6.7us across 9 structural variants with every
// unit <=30% utilized -> launch/ramp + single-wave fill/drain floor;
// v12's ILP-for-occupancy trade regressed, confirming resident-warp count
// is the binding latency-hiding resource.

static constexpr int F    = 15;           // membership functions per position
static constexpr int R    = 125;          // rules per position
static constexpr int G    = 16;           // positions per CTA
static constexpr int NLD4 = G * F / 4;    // 60 float4 input loads per CTA

__global__ void __launch_bounds__(128)
rules_fire_v11(const float4* __restrict__ x4, float* __restrict__ out)
{
    __shared__ float sx[G * F];           // 240 floats (16 rows x 15)

    const int t   = threadIdx.x;
    const int grp = blockIdx.x;

    // Stage 16x15 inputs (threads 0..59), zero->1 fix at load.
    if (t < NLD4) {
        float4 v = __ldg(&x4[(size_t)grp * NLD4 + t]);
        v.x = (v.x == 0.0f) ? 1.0f : v.x;
        v.y = (v.y == 0.0f) ? 1.0f : v.y;
        v.z = (v.z == 0.0f) ? 1.0f : v.z;
        v.w = (v.w == 0.0f) ? 1.0f : v.w;
        reinterpret_cast<float4*>(sx)[t] = v;
    }
    __syncthreads();

    if (t < R) {
        // One rule decomposition per thread — the only divisions in the kernel.
        const int q = t / 5;
        const int k = t - 5 * q;          // t % 5
        const int i = q / 5;
        const int j = q - 5 * i;          // (t/5) % 5

        const int oa = i;
        const int ob = 5 + j;
        const int oc = 10 + k;

        float* o = out + (size_t)grp * G * R + t;   // + p*R via immediates

        #pragma unroll
        for (int p = 0; p < G; p++) {
            const int rb = p * F;                   // LDS immediate
            const float r = sx[rb + oa] * sx[rb + ob] * sx[rb + oc];
            __stcs(o + p * R, r);                   // streaming (evict-first)
        }
    }
}

// Scalar fallback for positions past the last full group (unused for B=16,S=2048).
__global__ void rules_fire_tail(const float* __restrict__ x, float* __restrict__ out,
                                int pos0, int npos)
{
    const int pos = pos0 + blockIdx.x;
    if (pos >= npos) return;
    __shared__ float sxt[F + 1];
    const int t = threadIdx.x;
    if (t < F) {
        float v = x[(size_t)pos * F + t];
        sxt[t] = (v == 0.0f) ? 1.0f : v;
    }
    __syncthreads();
    if (t < R) {
        const int i = t / 25, j = (t / 5) % 5, k = t % 5;
        out[(size_t)pos * R + t] = sxt[i] * sxt[5 + j] * sxt[10 + k];
    }
}

extern "C" void kernel_launch(void* const* d_in, const int* in_sizes, int n_in,
                              void* d_out, int out_size)
{
    const float* x = (const float*)d_in[0];   // (B, S, 15) float32
    float* out = (float*)d_out;               // (B, S, 125) float32

    const int npos    = in_sizes[0] / F;      // 32768
    const int ngroups = npos / G;             // 2048
    if (ngroups > 0)
        rules_fire_v11<<<ngroups, 128>>>((const float4*)x, out);

    const int tail = npos - ngroups * G;
    if (tail > 0)
        rules_fire_tail<<<tail, 128>>>(x, out, ngroups * G, npos);
}